// round 1
// baseline (speedup 1.0000x reference)
#include <cuda_runtime.h>

// g[b,0,i,j] = cos(phi_i + phi_j) with phi = arccos(c)
//            = c_i*c_j - s_i*s_j,  s = sqrt(1 - c^2)
// c = clamp((2x - mx - mn)/(mx - mn), -1+eps, 1-eps) per batch row.

#define N 512
#define B 512
#define THREADS 256
#define CHUNKS 8                 // row-chunks per batch
#define ROWS_PER_CHUNK (N / CHUNKS)   // 64

__global__ __launch_bounds__(THREADS)
void gram_kernel(const float* __restrict__ x, float* __restrict__ out) {
    const int b = blockIdx.x;
    const int chunk = blockIdx.y;
    const int tid = threadIdx.x;

    __shared__ float sc[N];
    __shared__ float ss[N];
    __shared__ float wmn[8], wmx[8];
    __shared__ float red_mn, red_mx;

    const float* __restrict__ xb = x + (size_t)b * N;

    // Each thread loads 2 elements
    float v0 = __ldg(xb + tid);
    float v1 = __ldg(xb + tid + THREADS);

    float mn = fminf(v0, v1);
    float mx = fmaxf(v0, v1);
    #pragma unroll
    for (int o = 16; o > 0; o >>= 1) {
        mn = fminf(mn, __shfl_xor_sync(0xFFFFFFFFu, mn, o));
        mx = fmaxf(mx, __shfl_xor_sync(0xFFFFFFFFu, mx, o));
    }
    if ((tid & 31) == 0) { wmn[tid >> 5] = mn; wmx[tid >> 5] = mx; }
    __syncthreads();
    if (tid < 32) {
        float m1 = (tid < 8) ? wmn[tid] : 3.0e38f;
        float m2 = (tid < 8) ? wmx[tid] : -3.0e38f;
        #pragma unroll
        for (int o = 4; o > 0; o >>= 1) {
            m1 = fminf(m1, __shfl_xor_sync(0xFFFFFFFFu, m1, o));
            m2 = fmaxf(m2, __shfl_xor_sync(0xFFFFFFFFu, m2, o));
        }
        if (tid == 0) { red_mn = m1; red_mx = m2; }
    }
    __syncthreads();

    const float lo = red_mn, hi = red_mx;
    const float inv = 1.0f / (hi - lo);
    const float shift = hi + lo;
    const float EPS = 1e-6f;

    float c0 = (2.0f * v0 - shift) * inv;
    c0 = fminf(fmaxf(c0, -1.0f + EPS), 1.0f - EPS);
    float c1 = (2.0f * v1 - shift) * inv;
    c1 = fminf(fmaxf(c1, -1.0f + EPS), 1.0f - EPS);

    sc[tid]           = c0;
    ss[tid]           = sqrtf(fmaxf(1.0f - c0 * c0, 0.0f));
    sc[tid + THREADS] = c1;
    ss[tid + THREADS] = sqrtf(fmaxf(1.0f - c1 * c1, 0.0f));
    __syncthreads();

    // Write ROWS_PER_CHUNK rows x N cols as float4 (fully coalesced)
    const int row0 = chunk * ROWS_PER_CHUNK;
    float4* __restrict__ out4 =
        (float4*)(out + (size_t)b * N * N + (size_t)row0 * N);
    const float4* __restrict__ sc4 = (const float4*)sc;
    const float4* __restrict__ ss4 = (const float4*)ss;

    const int NV4 = N / 4;                       // 128 float4 per row
    const int TOTAL = ROWS_PER_CHUNK * NV4;      // 8192 per CTA

    #pragma unroll 4
    for (int idx = tid; idx < TOTAL; idx += THREADS) {
        const int row = idx >> 7;                // idx / 128
        const int j4  = idx & 127;               // col-group
        const float ci = sc[row0 + row];
        const float si = ss[row0 + row];
        const float4 cj = sc4[j4];
        const float4 sj = ss4[j4];
        float4 r;
        r.x = fmaf(ci, cj.x, -si * sj.x);
        r.y = fmaf(ci, cj.y, -si * sj.y);
        r.z = fmaf(ci, cj.z, -si * sj.z);
        r.w = fmaf(ci, cj.w, -si * sj.w);
        out4[idx] = r;
    }
}

extern "C" void kernel_launch(void* const* d_in, const int* in_sizes, int n_in,
                              void* d_out, int out_size) {
    const float* x = (const float*)d_in[0];
    float* out = (float*)d_out;
    dim3 grid(B, CHUNKS);
    gram_kernel<<<grid, THREADS>>>(x, out);
}

// round 2
// speedup vs baseline: 1.0477x; 1.0477x over previous
#include <cuda_runtime.h>

// g[b,0,i,j] = cos(phi_i + phi_j) with phi = arccos(c)
//            = c_i*c_j - s_i*s_j,  s = sqrt(1 - c^2)
// c = clamp((2x - mx - mn)/(mx - mn), -1+eps, 1-eps) per batch row.

#define N 512
#define B 512
#define THREADS 256
#define CHUNKS 8                      // row-chunks per batch
#define ROWS_PER_CHUNK (N / CHUNKS)   // 64

__global__ __launch_bounds__(THREADS)
void gram_kernel(const float* __restrict__ x, float* __restrict__ out) {
    const int b = blockIdx.x;
    const int chunk = blockIdx.y;
    const int tid = threadIdx.x;

    __shared__ float sc[N];
    __shared__ float ss[N];
    __shared__ float wmn[8], wmx[8];
    __shared__ float red_mn, red_mx;

    const float* __restrict__ xb = x + (size_t)b * N;

    // Each thread loads 2 elements
    float v0 = __ldg(xb + tid);
    float v1 = __ldg(xb + tid + THREADS);

    float mn = fminf(v0, v1);
    float mx = fmaxf(v0, v1);
    #pragma unroll
    for (int o = 16; o > 0; o >>= 1) {
        mn = fminf(mn, __shfl_xor_sync(0xFFFFFFFFu, mn, o));
        mx = fmaxf(mx, __shfl_xor_sync(0xFFFFFFFFu, mx, o));
    }
    if ((tid & 31) == 0) { wmn[tid >> 5] = mn; wmx[tid >> 5] = mx; }
    __syncthreads();
    if (tid < 32) {
        float m1 = (tid < 8) ? wmn[tid] : 3.0e38f;
        float m2 = (tid < 8) ? wmx[tid] : -3.0e38f;
        #pragma unroll
        for (int o = 4; o > 0; o >>= 1) {
            m1 = fminf(m1, __shfl_xor_sync(0xFFFFFFFFu, m1, o));
            m2 = fmaxf(m2, __shfl_xor_sync(0xFFFFFFFFu, m2, o));
        }
        if (tid == 0) { red_mn = m1; red_mx = m2; }
    }
    __syncthreads();

    const float lo = red_mn, hi = red_mx;
    const float inv = 1.0f / (hi - lo);
    const float shift = hi + lo;
    const float EPS = 1e-6f;

    float c0 = (2.0f * v0 - shift) * inv;
    c0 = fminf(fmaxf(c0, -1.0f + EPS), 1.0f - EPS);
    float c1 = (2.0f * v1 - shift) * inv;
    c1 = fminf(fmaxf(c1, -1.0f + EPS), 1.0f - EPS);

    sc[tid]           = c0;
    ss[tid]           = sqrtf(fmaxf(1.0f - c0 * c0, 0.0f));
    sc[tid + THREADS] = c1;
    ss[tid + THREADS] = sqrtf(fmaxf(1.0f - c1 * c1, 0.0f));
    __syncthreads();

    // Each thread owns a fixed float4 column group; loop over rows.
    // cj/sj live in registers for the whole loop; ci/si are broadcast LDS.
    const int row0 = chunk * ROWS_PER_CHUNK;
    const int col  = tid & 127;          // float4 column index 0..127
    const int half = tid >> 7;           // 0 or 1: which row parity

    const float4 cj = ((const float4*)sc)[col];
    const float4 sj = ((const float4*)ss)[col];

    float4* __restrict__ out4 =
        (float4*)(out + (size_t)b * N * N + (size_t)row0 * N);

    // 64 rows, 2 halves -> 32 rows per thread; unroll 8
    #pragma unroll 8
    for (int r = half; r < ROWS_PER_CHUNK; r += 2) {
        const float ci = sc[row0 + r];
        const float si = ss[row0 + r];
        float4 rv;
        rv.x = fmaf(ci, cj.x, -si * sj.x);
        rv.y = fmaf(ci, cj.y, -si * sj.y);
        rv.z = fmaf(ci, cj.z, -si * sj.z);
        rv.w = fmaf(ci, cj.w, -si * sj.w);
        __stcs(&out4[r * 128 + col], rv);
    }
}

extern "C" void kernel_launch(void* const* d_in, const int* in_sizes, int n_in,
                              void* d_out, int out_size) {
    const float* x = (const float*)d_in[0];
    float* out = (float*)d_out;
    dim3 grid(B, CHUNKS);
    gram_kernel<<<grid, THREADS>>>(x, out);
}